// round 11
// baseline (speedup 1.0000x reference)
#include <cuda_runtime.h>

#define BATCH   8
#define NPTS    8192
#define CIN     64
#define CMID    128
#define NSAMP   2048
#define KNNK    32
#define NGRP    (BATCH*NSAMP)        /* 16384 */
#define PELEMS  (CMID*NSAMP)         /* 262144 */

#define XS_STRIDE 132                /* pos kernel row stride */
#define CST       68                 /* fused kernel row stride (64 cols + pad) */

// -------- scratch (static device globals; no allocation APIs) --------
__device__ float  g_bufP[(size_t)BATCH * PELEMS];  // 8.4 MB
__device__ float  g_bufD[(size_t)BATCH * PELEMS];  // 8.4 MB
__device__ int    g_fps[NGRP];
__device__ int    g_knn[NGRP * KNNK];
__device__ float2 g_wt2[9 * 16384 + 128];          // transposed+duplicated W + pad

// Bit-exact match to XLA's un-contracted  (dx*dx + dy*dy) + dz*dz
__device__ __forceinline__ float sqdist(float dx, float dy, float dz)
{
    float a = __fmul_rn(dx, dx);
    float b = __fmul_rn(dy, dy);
    float c = __fmul_rn(dz, dz);
    return __fadd_rn(__fadd_rn(a, b), c);
}

__device__ __forceinline__ unsigned redux_max_u32(unsigned v)
{
    unsigned r;
    asm("redux.sync.max.u32 %0, %1, 0xffffffff;" : "=r"(r) : "r"(v));
    return r;
}

#define FFMA2(acc, a, b) \
    asm("fma.rn.f32x2 %0, %1, %2, %3;" : "=l"(acc) : "l"(a), "l"(b), "l"(acc))
#define UNPACK64(lo, hi, v) \
    asm("mov.b64 {%0, %1}, %2;" : "=r"(lo), "=r"(hi) : "l"(v))

// ====================================================================
// Weight pre-transform: Wt2[s][c][o] = {W_s[o][c], W_s[o][c]}
// ====================================================================
struct WPtrs { const float* w[9]; };
__global__ __launch_bounds__(256) void wtrans_kernel(WPtrs p, float2* __restrict__ out)
{
    int idx = blockIdx.x * 256 + threadIdx.x;         // 9*16384 total
    int s = idx >> 14, r = idx & 16383;
    int o = r >> 7, c = r & 127;
    float w = p.w[s][o * 128 + c];
    out[(s << 14) + c * 128 + o] = make_float2(w, w);
}

// ====================================================================
// FPS: one block/batch, 1024 threads, 8 pts/thread, 1 barrier/step.
// ====================================================================
__global__ __launch_bounds__(1024) void fps_kernel(const float* __restrict__ xyz,
                                                   float* __restrict__ newxyz,
                                                   int* __restrict__ fpsIdx)
{
    extern __shared__ float fsm[];
    float* sx = fsm;
    float* sy = fsm + NPTS;
    float* sz = fsm + 2*NPTS;
    float* s_val2 = fsm + 3*NPTS;           // [2][32]
    int*   s_idx2 = (int*)(fsm + 3*NPTS + 64);

    const int b = blockIdx.x;
    const int t = threadIdx.x;
    const int lane = t & 31;
    const int warp = t >> 5;
    const float* base = xyz + (size_t)b * NPTS * 3;

    float px[8], py[8], pz[8], dist[8];
#pragma unroll
    for (int j = 0; j < 8; j++) {
        int p = j * 1024 + t;
        float x = base[p*3+0], y = base[p*3+1], z = base[p*3+2];
        px[j] = x; py[j] = y; pz[j] = z;
        sx[p] = x; sy[p] = y; sz[p] = z;
        dist[j] = 1e10f;
    }

    if (t == 0) {
        fpsIdx[b*NSAMP] = 0;
        newxyz[(size_t)b*NSAMP*3 + 0] = px[0];
        newxyz[(size_t)b*NSAMP*3 + 1] = py[0];
        newxyz[(size_t)b*NSAMP*3 + 2] = pz[0];
    }
    __syncthreads();

    int w = 0;
    for (int s = 1; s < NSAMP; s++) {
        const float qx = sx[w], qy = sy[w], qz = sz[w];
        float bv = -1.0f; int bj = 0;
#pragma unroll
        for (int j = 0; j < 8; j++) {
            float d = sqdist(px[j]-qx, py[j]-qy, pz[j]-qz);
            d = fminf(dist[j], d);
            dist[j] = d;
            if (d > bv) { bv = d; bj = j; }
        }
        int gi = bj*1024 + t;
        unsigned ub = __float_as_uint(bv);
        unsigned mx = redux_max_u32(ub);
        unsigned bl = __ballot_sync(0xffffffffu, ub == mx);
        int src = __ffs(bl) - 1;
        int wgi = __shfl_sync(0xffffffffu, gi, src);

        const int par = (s & 1) * 32;
        if (lane == 0) { s_val2[par + warp] = __uint_as_float(mx); s_idx2[par + warp] = wgi; }
        __syncthreads();

        unsigned v2 = __float_as_uint(s_val2[par + lane]);
        int      i2 = s_idx2[par + lane];
        unsigned m2 = redux_max_u32(v2);
        unsigned b2 = __ballot_sync(0xffffffffu, v2 == m2);
        int s2 = __ffs(b2) - 1;
        w = __shfl_sync(0xffffffffu, i2, s2);

        if (t == 0) {
            fpsIdx[b*NSAMP + s] = w;
            size_t o = ((size_t)b*NSAMP + s)*3;
            newxyz[o+0] = sx[w]; newxyz[o+1] = sy[w]; newxyz[o+2] = sz[w];
        }
    }
}

// ====================================================================
// KNN: 256 blocks, warp-per-sample sorted top-32.
// ====================================================================
__global__ __launch_bounds__(256) void knn_kernel(const float* __restrict__ xyz,
                                                  const float* __restrict__ newxyz,
                                                  int* __restrict__ knnIdx)
{
    extern __shared__ float sm[];
    float* sx = sm; float* sy = sm + NPTS; float* sz = sm + 2*NPTS;
    const int b    = blockIdx.x >> 5;
    const int tile = blockIdx.x & 31;
    const float* base = xyz + (size_t)b * NPTS * 3;
    for (int i = threadIdx.x; i < NPTS; i += 256) {
        sx[i] = base[i*3+0]; sy[i] = base[i*3+1]; sz[i] = base[i*3+2];
    }
    __syncthreads();

    const int lane = threadIdx.x & 31;
    const int warp = threadIdx.x >> 5;

    for (int rep = 0; rep < 8; rep++) {
        const int s = tile*64 + warp*8 + rep;
        const float* q = newxyz + ((size_t)b*NSAMP + s)*3;
        const float qx = q[0], qy = q[1], qz = q[2];
        float lval = 1e30f; int lidx = 0;
        float thr  = 1e30f;

        for (int j0 = 0; j0 < NPTS/32; j0++) {
            const int p = j0*32 + lane;
            float d = sqdist(sx[p]-qx, sy[p]-qy, sz[p]-qz);
            unsigned m = __ballot_sync(0xffffffffu, d < thr);
            if (m) {
                while (m) {
                    int src = __ffs(m) - 1; m &= m - 1;
                    float cd = __shfl_sync(0xffffffffu, d, src);
                    int   cj = __shfl_sync(0xffffffffu, p, src);
                    float pv = __shfl_up_sync(0xffffffffu, lval, 1);
                    int   pi = __shfl_up_sync(0xffffffffu, lidx, 1);
                    bool shift  = lval > cd;
                    bool pshift = (lane > 0) && (pv > cd);
                    lval = shift ? (pshift ? pv : cd) : lval;
                    lidx = shift ? (pshift ? pi : cj) : lidx;
                }
                thr = __shfl_sync(0xffffffffu, lval, 31);
            }
        }
        knnIdx[((size_t)b*NSAMP + s)*KNNK + lane] = lidx;
    }
}

// ====================================================================
// FUSED pre-chain: gather -> te -> pre1 -> pre2 -> maxpool.
// One CTA owns 64 columns (2 groups) through all 5 stages in smem.
// Thread map: tx=tid&7 (cols tx*8..+7), ty=tid>>3 (o=ty*4..+3).
// Per thread-kc: 2 LDS.128 + 2 LDG.128 (W, warp covers one 128B line)
// + 16 FFMA2  -> same 2B-W/FFMA2 ratio as the proven R8 kernel.
// ====================================================================
struct BNP { const float* g[5]; const float* b[5]; const float* m[5]; const float* v[5]; };

__global__ __launch_bounds__(256, 3) void fused_pre_kernel(
    const float* __restrict__ feat, const int* __restrict__ knnIdx,
    const int* __restrict__ fpsIdx, const float2* __restrict__ Wt2,
    BNP bp, float* __restrict__ P)
{
    extern __shared__ float sm[];
    float* bufA    = sm;                    // [128][68]
    float* bufB    = sm + 128*CST;
    float* s_scale = sm + 2*128*CST;        // [2][128]
    float* s_shift = s_scale + 256;

    const int tid   = threadIdx.x;
    const int gbase = blockIdx.x * 2;       // 2 groups per CTA
    const int b     = gbase >> 11;
    const float* fb = feat + (size_t)b * NPTS * CIN;

    // ---- gather: neighbor rows c 0..63, cols 0..63 ----
#pragma unroll
    for (int it = 0; it < 16; it++) {
        int e = tid + it*256;
        int c = e >> 6, col = e & 63;
        int p = __ldg(&knnIdx[(gbase + (col >> 5))*KNNK + (col & 31)]);
        bufA[c*CST + col] = fb[p*CIN + c];
    }
    // ---- center rows c 64..127, replicated over each group's 32 cols ----
    if (tid < 128) {
        int c = tid & 63, grp = tid >> 6;
        float v = fb[__ldg(&fpsIdx[gbase + grp])*CIN + c];
        float4 vv = make_float4(v, v, v, v);
        float4* row = (float4*)(bufA + (64 + c)*CST + grp*32);
#pragma unroll
        for (int k4 = 0; k4 < 8; k4++) row[k4] = vv;
    }

    const int tx = tid & 7, ty = tid >> 3;      // 8 col-threads x 32 o-groups
    float* bufIn  = bufA;
    float* bufOut = bufB;

    for (int s = 0; s < 5; s++) {
        const int par = (s & 1) * 128;
        if (tid < 128) {
            float sc = bp.g[s][tid] / sqrtf(bp.v[s][tid] + 1e-5f);
            s_scale[par + tid] = sc;
            s_shift[par + tid] = bp.b[s][tid] - bp.m[s][tid] * sc;
        }
        __syncthreads();   // covers prev-stage writes + gather + scales

        unsigned long long acc[4][4];           // [o][colpair]
#pragma unroll
        for (int i = 0; i < 4; i++)
#pragma unroll
            for (int j = 0; j < 4; j++) acc[i][j] = 0ull;

        const float* XsC = bufIn + tx*8;
        const ulonglong2* __restrict__ Wc = (const ulonglong2*)(Wt2 + (s << 14) + ty*4);

        ulonglong2 w01 = __ldg(Wc);             // outputs ty*4+0, +1
        ulonglong2 w23 = __ldg(Wc + 1);         // outputs ty*4+2, +3

#pragma unroll 2
        for (int kc = 0; kc < 128; kc++) {
            ulonglong2 xa = *(const ulonglong2*)(XsC + kc*CST);       // cols tx*8..+3
            ulonglong2 xb = *(const ulonglong2*)(XsC + kc*CST + 4);   // cols tx*8+4..+7
            const ulonglong2* wn = Wc + (kc + 1)*64;                  // prefetch (pad ok)
            ulonglong2 n01 = __ldg(wn);
            ulonglong2 n23 = __ldg(wn + 1);
            unsigned long long wv[4] = {w01.x, w01.y, w23.x, w23.y};
            unsigned long long xp[4] = {xa.x, xa.y, xb.x, xb.y};
#pragma unroll
            for (int i = 0; i < 4; i++)
#pragma unroll
                for (int j = 0; j < 4; j++)
                    FFMA2(acc[i][j], wv[i], xp[j]);
            w01 = n01; w23 = n23;
        }

        const bool res  = (s == 2) || (s == 4);
        const bool pool = (s == 4);
#pragma unroll
        for (int i = 0; i < 4; i++) {
            const int o = ty*4 + i;
            const float sc = s_scale[par + o], sh = s_shift[par + o];
            float v[8];
#pragma unroll
            for (int j = 0; j < 4; j++) {
                unsigned lo, hi;
                UNPACK64(lo, hi, acc[i][j]);
                v[2*j]   = __uint_as_float(lo);
                v[2*j+1] = __uint_as_float(hi);
            }
#pragma unroll
            for (int c = 0; c < 8; c++) v[c] = fmaf(v[c], sc, sh);
            if (res) {
                float4 r0 = *(const float4*)(bufOut + o*CST + tx*8);
                float4 r1 = *(const float4*)(bufOut + o*CST + tx*8 + 4);
                v[0]+=r0.x; v[1]+=r0.y; v[2]+=r0.z; v[3]+=r0.w;
                v[4]+=r1.x; v[5]+=r1.y; v[6]+=r1.z; v[7]+=r1.w;
            }
#pragma unroll
            for (int c = 0; c < 8; c++) v[c] = fmaxf(v[c], 0.f);

            if (pool) {
                float m = v[0];
#pragma unroll
                for (int c = 1; c < 8; c++) m = fmaxf(m, v[c]);
                m = fmaxf(m, __shfl_xor_sync(0xffffffffu, m, 1));
                m = fmaxf(m, __shfl_xor_sync(0xffffffffu, m, 2));
                if ((tx & 3) == 0) {                  // tx 0 -> group 0, tx 4 -> group 1
                    int g = gbase + (tx >> 2);
                    int bb = g >> 11, ss = g & 2047;
                    P[((bb << 7) + o) * 2048 + ss] = m;
                }
            } else {
                *(float4*)(bufOut + o*CST + tx*8)     = make_float4(v[0],v[1],v[2],v[3]);
                *(float4*)(bufOut + o*CST + tx*8 + 4) = make_float4(v[4],v[5],v[6],v[7]);
            }
        }
        float* t2 = bufIn; bufIn = bufOut; bufOut = t2;
    }
}

// ====================================================================
// pos conv (R8-proven form): 128-col tile, FFMA2 col-pairs,
// pre-duplicated W via LDG with prefetch. kls = 11.
// ====================================================================
__global__ __launch_bounds__(256, 2) void conv_bn_pos(
    const float* __restrict__ X, const float2* __restrict__ Wt2,
    const float* __restrict__ gam, const float* __restrict__ bet,
    const float* __restrict__ mu,  const float* __restrict__ var,
    const float* __restrict__ R,   float* __restrict__ Y)
{
    extern __shared__ float sm[];
    float* Xs      = sm;                       // [c][col], stride 132
    float* s_scale = sm + 128*XS_STRIDE;
    float* s_shift = s_scale + 128;

    const int tid  = threadIdx.x;
    const int klen = 2048;
    const int n0   = blockIdx.x << 7;

    for (int idx = tid; idx < 16384; idx += 256) {
        int c = idx >> 7, col = idx & 127;
        int n = n0 + col;
        int g = n >> 11, k = n & (klen-1);
        Xs[c*XS_STRIDE + col] = X[((g << 7) + c) * klen + k];
    }
    if (tid < 128) {
        float sc = gam[tid] / sqrtf(var[tid] + 1e-5f);
        s_scale[tid] = sc;
        s_shift[tid] = bet[tid] - mu[tid] * sc;
    }
    __syncthreads();

    const int tx = tid & 15, ty = tid >> 4;
    unsigned long long acc[8][4];
#pragma unroll
    for (int i = 0; i < 8; i++)
#pragma unroll
        for (int j = 0; j < 4; j++) acc[i][j] = 0ull;

    const float* XsC = Xs + tx*4;
    const ulonglong2* __restrict__ Wc = (const ulonglong2*)(Wt2 + ty*8);

    ulonglong2 w01 = __ldg(Wc);
    ulonglong2 w23 = __ldg(Wc + 1);
    ulonglong2 w45 = __ldg(Wc + 2);
    ulonglong2 w67 = __ldg(Wc + 3);

#pragma unroll 2
    for (int kc = 0; kc < 128; kc++) {
        ulonglong2 xa = *(const ulonglong2*)(XsC + kc*XS_STRIDE);
        ulonglong2 xb = *(const ulonglong2*)(XsC + kc*XS_STRIDE + 64);
        const ulonglong2* wn = Wc + (kc + 1)*64;
        ulonglong2 n01 = __ldg(wn);
        ulonglong2 n23 = __ldg(wn + 1);
        ulonglong2 n45 = __ldg(wn + 2);
        ulonglong2 n67 = __ldg(wn + 3);
        unsigned long long wv[8] = {w01.x, w01.y, w23.x, w23.y, w45.x, w45.y, w67.x, w67.y};
        unsigned long long xp[4] = {xa.x, xa.y, xb.x, xb.y};
#pragma unroll
        for (int i = 0; i < 8; i++)
#pragma unroll
            for (int j = 0; j < 4; j++)
                FFMA2(acc[i][j], wv[i], xp[j]);
        w01 = n01; w23 = n23; w45 = n45; w67 = n67;
    }

    const int ncolA = n0 + tx*4;
    const int ncolB = ncolA + 64;
    const int gA = ncolA >> 11, kA = ncolA & (klen-1);
    const int gB = ncolB >> 11, kB = ncolB & (klen-1);
#pragma unroll
    for (int i = 0; i < 8; i++) {
        const int o = ty*8 + i;
        const float sc = s_scale[o], sh = s_shift[o];
        const int addrA = ((gA << 7) + o) * klen + kA;
        const int addrB = ((gB << 7) + o) * klen + kB;
        float v[8];
#pragma unroll
        for (int j = 0; j < 4; j++) {
            unsigned lo, hi;
            UNPACK64(lo, hi, acc[i][j]);
            v[2*j]   = __uint_as_float(lo);
            v[2*j+1] = __uint_as_float(hi);
        }
#pragma unroll
        for (int j = 0; j < 8; j++) v[j] = fmaf(v[j], sc, sh);
        if (R) {
            float4 rA = *(const float4*)(R + addrA);
            float4 rB = *(const float4*)(R + addrB);
            v[0]+=rA.x; v[1]+=rA.y; v[2]+=rA.z; v[3]+=rA.w;
            v[4]+=rB.x; v[5]+=rB.y; v[6]+=rB.z; v[7]+=rB.w;
        }
#pragma unroll
        for (int j = 0; j < 8; j++) v[j] = fmaxf(v[j], 0.f);
        *(float4*)(Y + addrA) = make_float4(v[0],v[1],v[2],v[3]);
        *(float4*)(Y + addrB) = make_float4(v[4],v[5],v[6],v[7]);
    }
}

// ====================================================================
extern "C" void kernel_launch(void* const* d_in, const int* in_sizes, int n_in,
                              void* d_out, int out_size)
{
    // setup_inputs() dict-insertion order
    const float* xyz    = (const float*)d_in[0];
    const float* feat   = (const float*)d_in[1];
    const float* te_w   = (const float*)d_in[2];
    const float* te_g   = (const float*)d_in[3];
    const float* te_b   = (const float*)d_in[4];
    const float* te_m   = (const float*)d_in[5];
    const float* te_v   = (const float*)d_in[6];
    const float* pre_w1 = (const float*)d_in[7];
    const float* pre_w2 = (const float*)d_in[8];
    const float* pre_g1 = (const float*)d_in[9];
    const float* pre_g2 = (const float*)d_in[10];
    const float* pre_b1 = (const float*)d_in[11];
    const float* pre_b2 = (const float*)d_in[12];
    const float* pre_m1 = (const float*)d_in[13];
    const float* pre_m2 = (const float*)d_in[14];
    const float* pre_v1 = (const float*)d_in[15];
    const float* pre_v2 = (const float*)d_in[16];
    const float* pos_w1 = (const float*)d_in[17];
    const float* pos_w2 = (const float*)d_in[18];
    const float* pos_g1 = (const float*)d_in[19];
    const float* pos_g2 = (const float*)d_in[20];
    const float* pos_b1 = (const float*)d_in[21];
    const float* pos_b2 = (const float*)d_in[22];
    const float* pos_m1 = (const float*)d_in[23];
    const float* pos_m2 = (const float*)d_in[24];
    const float* pos_v1 = (const float*)d_in[25];
    const float* pos_v2 = (const float*)d_in[26];

    float* out_xyz = (float*)d_out;                    // (8,2048,3)
    float* out_x   = (float*)d_out + BATCH*NSAMP*3;    // (8,128,2048)

    float *P, *D; int *fp, *kn; float2 *wt;
    cudaGetSymbolAddress((void**)&P,  g_bufP);
    cudaGetSymbolAddress((void**)&D,  g_bufD);
    cudaGetSymbolAddress((void**)&fp, g_fps);
    cudaGetSymbolAddress((void**)&kn, g_knn);
    cudaGetSymbolAddress((void**)&wt, g_wt2);

    const int FPS_SMEM   = (3*NPTS + 128) * 4;             // ~99 KB
    const int KNN_SMEM   = 3 * NPTS * 4;                   // 96 KB
    const int FUSED_SMEM = (2*128*CST + 512) * 4;          // 71680 B
    const int POS_SMEM   = (128*XS_STRIDE + 256) * 4;      // ~68.6 KB
    cudaFuncSetAttribute(fps_kernel,       cudaFuncAttributeMaxDynamicSharedMemorySize, FPS_SMEM);
    cudaFuncSetAttribute(knn_kernel,       cudaFuncAttributeMaxDynamicSharedMemorySize, KNN_SMEM);
    cudaFuncSetAttribute(fused_pre_kernel, cudaFuncAttributeMaxDynamicSharedMemorySize, FUSED_SMEM);
    cudaFuncSetAttribute(conv_bn_pos,      cudaFuncAttributeMaxDynamicSharedMemorySize, POS_SMEM);

    // weight pre-transform (stage order: te, pw1[0], pw2[0], pw1[1], pw2[1], qw1[0], qw2[0], qw1[1], qw2[1])
    WPtrs wp;
    wp.w[0] = te_w;
    wp.w[1] = pre_w1;          wp.w[2] = pre_w2;
    wp.w[3] = pre_w1 + 16384;  wp.w[4] = pre_w2 + 16384;
    wp.w[5] = pos_w1;          wp.w[6] = pos_w2;
    wp.w[7] = pos_w1 + 16384;  wp.w[8] = pos_w2 + 16384;
    wtrans_kernel<<<(9*16384)/256, 256>>>(wp, wt);

    fps_kernel<<<BATCH, 1024, FPS_SMEM>>>(xyz, out_xyz, fp);
    knn_kernel<<<256, 256, KNN_SMEM>>>(xyz, out_xyz, kn);

    // fused te + pre res-blocks + maxpool: 8192 CTAs x 64 cols
    BNP bp;
    bp.g[0]=te_g;  bp.b[0]=te_b;  bp.m[0]=te_m;  bp.v[0]=te_v;
    bp.g[1]=pre_g1;      bp.b[1]=pre_b1;      bp.m[1]=pre_m1;      bp.v[1]=pre_v1;
    bp.g[2]=pre_g2;      bp.b[2]=pre_b2;      bp.m[2]=pre_m2;      bp.v[2]=pre_v2;
    bp.g[3]=pre_g1+128;  bp.b[3]=pre_b1+128;  bp.m[3]=pre_m1+128;  bp.v[3]=pre_v1+128;
    bp.g[4]=pre_g2+128;  bp.b[4]=pre_b2+128;  bp.m[4]=pre_m2+128;  bp.v[4]=pre_v2+128;
    fused_pre_kernel<<<NGRP/2, 256, FUSED_SMEM>>>(feat, kn, fp, wt, bp, P);

    // pos: 2 res-blocks on (8,128,2048); 16384 cols
    conv_bn_pos<<<128, 256, POS_SMEM>>>(P, wt + 5*16384, pos_g1,     pos_b1,     pos_m1,     pos_v1,     nullptr, D);
    conv_bn_pos<<<128, 256, POS_SMEM>>>(D, wt + 6*16384, pos_g2,     pos_b2,     pos_m2,     pos_v2,     P,       P);
    conv_bn_pos<<<128, 256, POS_SMEM>>>(P, wt + 7*16384, pos_g1+128, pos_b1+128, pos_m1+128, pos_v1+128, nullptr, D);
    conv_bn_pos<<<128, 256, POS_SMEM>>>(D, wt + 8*16384, pos_g2+128, pos_b2+128, pos_m2+128, pos_v2+128, P,       out_x);
}

// round 12
// speedup vs baseline: 2.0367x; 2.0367x over previous
#include <cuda_runtime.h>

#define BATCH   8
#define NPTS    8192
#define CIN     64
#define CMID    128
#define NSAMP   2048
#define KNNK    32
#define NGRP    (BATCH*NSAMP)        /* 16384 */
#define GELEMS  (CMID*KNNK)          /* 4096  */
#define PELEMS  (CMID*NSAMP)         /* 262144 */

#define XS_STRIDE 132                /* padded row stride (floats) */

// -------- scratch (static device globals; no allocation APIs) --------
__device__ float  g_bufA[(size_t)NGRP * GELEMS];   // 268 MB
__device__ float  g_bufB[(size_t)NGRP * GELEMS];   // 268 MB
__device__ float  g_bufP[(size_t)BATCH * PELEMS];  // 8.4 MB
__device__ float  g_bufD[(size_t)BATCH * PELEMS];  // 8.4 MB
__device__ int    g_fps[NGRP];
__device__ int    g_knn[NGRP * KNNK];
__device__ float2 g_wt2[9 * 16384 + 128];          // transposed+duplicated W + pad

// Bit-exact match to XLA's un-contracted  (dx*dx + dy*dy) + dz*dz
__device__ __forceinline__ float sqdist(float dx, float dy, float dz)
{
    float a = __fmul_rn(dx, dx);
    float b = __fmul_rn(dy, dy);
    float c = __fmul_rn(dz, dz);
    return __fadd_rn(__fadd_rn(a, b), c);
}

__device__ __forceinline__ unsigned redux_max_u32(unsigned v)
{
    unsigned r;
    asm("redux.sync.max.u32 %0, %1, 0xffffffff;" : "=r"(r) : "r"(v));
    return r;
}

#define FFMA2(acc, a, b) \
    asm("fma.rn.f32x2 %0, %1, %2, %3;" : "=l"(acc) : "l"(a), "l"(b), "l"(acc))
#define ADD2(d, a, b) \
    asm("add.rn.f32x2 %0, %1, %2;" : "=l"(d) : "l"(a), "l"(b))
#define MUL2(d, a, b) \
    asm("mul.rn.f32x2 %0, %1, %2;" : "=l"(d) : "l"(a), "l"(b))
#define PACK2(d, lo, hi) \
    asm("mov.b64 %0, {%1, %2};" : "=l"(d) : "r"(__float_as_uint(lo)), "r"(__float_as_uint(hi)))
#define PACKDUP(d, f) \
    asm("mov.b64 %0, {%1, %1};" : "=l"(d) : "r"(__float_as_uint(f)))
#define UNPACK64(lo, hi, v) \
    asm("mov.b64 {%0, %1}, %2;" : "=r"(lo), "=r"(hi) : "l"(v))

// ====================================================================
// Weight pre-transform: Wt2[s][c][o] = {W_s[o][c], W_s[o][c]}
// ====================================================================
struct WPtrs { const float* w[9]; };
__global__ __launch_bounds__(256) void wtrans_kernel(WPtrs p, float2* __restrict__ out)
{
    int idx = blockIdx.x * 256 + threadIdx.x;         // 9*16384 total
    int s = idx >> 14, r = idx & 16383;
    int o = r >> 7, c = r & 127;
    float w = p.w[s][o * 128 + c];
    out[(s << 14) + c * 128 + o] = make_float2(w, w);
}

// ====================================================================
// FPS: one block/batch, 1024 threads, 8 pts/thread, 1 barrier/step.
// Packed f32x2 distance math (bit-exact: .rn packed == scalar rn;
// px + (-qx) == px - qx). Tie-break: ascending j, strict > keeps
// lowest index (jnp.argmax first-occurrence).
// ====================================================================
__global__ __launch_bounds__(1024) void fps_kernel(const float* __restrict__ xyz,
                                                   float* __restrict__ newxyz,
                                                   int* __restrict__ fpsIdx)
{
    extern __shared__ float fsm[];
    float* sx = fsm;
    float* sy = fsm + NPTS;
    float* sz = fsm + 2*NPTS;
    float* s_val2 = fsm + 3*NPTS;           // [2][32]
    int*   s_idx2 = (int*)(fsm + 3*NPTS + 64);

    const int b = blockIdx.x;
    const int t = threadIdx.x;
    const int lane = t & 31;
    const int warp = t >> 5;
    const float* base = xyz + (size_t)b * NPTS * 3;

    // packed pairs: slot u holds points j=2u (lo) and j=2u+1 (hi)
    unsigned long long ppx[4], ppy[4], ppz[4], pdd[4];
    float fx0 = 0.f, fy0 = 0.f, fz0 = 0.f;
#pragma unroll
    for (int u = 0; u < 4; u++) {
        int p0 = (2*u) * 1024 + t;
        int p1 = (2*u + 1) * 1024 + t;
        float x0 = base[p0*3+0], y0 = base[p0*3+1], z0 = base[p0*3+2];
        float x1 = base[p1*3+0], y1 = base[p1*3+1], z1 = base[p1*3+2];
        PACK2(ppx[u], x0, x1);
        PACK2(ppy[u], y0, y1);
        PACK2(ppz[u], z0, z1);
        sx[p0] = x0; sy[p0] = y0; sz[p0] = z0;
        sx[p1] = x1; sy[p1] = y1; sz[p1] = z1;
        PACKDUP(pdd[u], 1e10f);
        if (u == 0) { fx0 = x0; fy0 = y0; fz0 = z0; }
    }

    if (t == 0) {
        fpsIdx[b*NSAMP] = 0;
        newxyz[(size_t)b*NSAMP*3 + 0] = fx0;
        newxyz[(size_t)b*NSAMP*3 + 1] = fy0;
        newxyz[(size_t)b*NSAMP*3 + 2] = fz0;
    }
    __syncthreads();

    int w = 0;
    for (int s = 1; s < NSAMP; s++) {
        unsigned long long nqx2, nqy2, nqz2;
        {
            float nqx = -sx[w], nqy = -sy[w], nqz = -sz[w];
            PACKDUP(nqx2, nqx); PACKDUP(nqy2, nqy); PACKDUP(nqz2, nqz);
        }
        float bv = -1.0f; int bj = 0;
#pragma unroll
        for (int u = 0; u < 4; u++) {
            unsigned long long dx, dy, dz, ss;
            ADD2(dx, ppx[u], nqx2);       // px - qx
            ADD2(dy, ppy[u], nqy2);
            ADD2(dz, ppz[u], nqz2);
            MUL2(dx, dx, dx);
            MUL2(dy, dy, dy);
            MUL2(dz, dz, dz);
            ADD2(ss, dx, dy);
            ADD2(ss, ss, dz);
            unsigned d0b, d1b, e0b, e1b;
            UNPACK64(d0b, d1b, ss);
            UNPACK64(e0b, e1b, pdd[u]);
            float e0 = fminf(__uint_as_float(e0b), __uint_as_float(d0b));
            float e1 = fminf(__uint_as_float(e1b), __uint_as_float(d1b));
            PACK2(pdd[u], e0, e1);
            if (e0 > bv) { bv = e0; bj = 2*u; }      // ascending j: lowest-index ties
            if (e1 > bv) { bv = e1; bj = 2*u + 1; }
        }
        int gi = (bj << 10) | t;
        unsigned ub = __float_as_uint(bv);
        unsigned mx = redux_max_u32(ub);
        unsigned bl = __ballot_sync(0xffffffffu, ub == mx);
        int src = __ffs(bl) - 1;
        int wgi = __shfl_sync(0xffffffffu, gi, src);

        const int par = (s & 1) * 32;
        if (lane == 0) { s_val2[par + warp] = __uint_as_float(mx); s_idx2[par + warp] = wgi; }
        __syncthreads();

        unsigned v2 = __float_as_uint(s_val2[par + lane]);
        int      i2 = s_idx2[par + lane];
        unsigned m2 = redux_max_u32(v2);
        unsigned b2 = __ballot_sync(0xffffffffu, v2 == m2);
        int s2 = __ffs(b2) - 1;
        w = __shfl_sync(0xffffffffu, i2, s2);

        if (t == 0) {
            fpsIdx[b*NSAMP + s] = w;
            size_t o = ((size_t)b*NSAMP + s)*3;
            newxyz[o+0] = sx[w]; newxyz[o+1] = sy[w]; newxyz[o+2] = sz[w];
        }
    }
}

// ====================================================================
// KNN: 256 blocks, warp-per-sample sorted top-32.
// ====================================================================
__global__ __launch_bounds__(256) void knn_kernel(const float* __restrict__ xyz,
                                                  const float* __restrict__ newxyz,
                                                  int* __restrict__ knnIdx)
{
    extern __shared__ float sm[];
    float* sx = sm; float* sy = sm + NPTS; float* sz = sm + 2*NPTS;
    const int b    = blockIdx.x >> 5;
    const int tile = blockIdx.x & 31;
    const float* base = xyz + (size_t)b * NPTS * 3;
    for (int i = threadIdx.x; i < NPTS; i += 256) {
        sx[i] = base[i*3+0]; sy[i] = base[i*3+1]; sz[i] = base[i*3+2];
    }
    __syncthreads();

    const int lane = threadIdx.x & 31;
    const int warp = threadIdx.x >> 5;

    for (int rep = 0; rep < 8; rep++) {
        const int s = tile*64 + warp*8 + rep;
        const float* q = newxyz + ((size_t)b*NSAMP + s)*3;
        const float qx = q[0], qy = q[1], qz = q[2];
        float lval = 1e30f; int lidx = 0;
        float thr  = 1e30f;

        for (int j0 = 0; j0 < NPTS/32; j0++) {
            const int p = j0*32 + lane;
            float d = sqdist(sx[p]-qx, sy[p]-qy, sz[p]-qz);
            unsigned m = __ballot_sync(0xffffffffu, d < thr);
            if (m) {
                while (m) {
                    int src = __ffs(m) - 1; m &= m - 1;
                    float cd = __shfl_sync(0xffffffffu, d, src);
                    int   cj = __shfl_sync(0xffffffffu, p, src);
                    float pv = __shfl_up_sync(0xffffffffu, lval, 1);
                    int   pi = __shfl_up_sync(0xffffffffu, lidx, 1);
                    bool shift  = lval > cd;
                    bool pshift = (lane > 0) && (pv > cd);
                    lval = shift ? (pshift ? pv : cd) : lval;
                    lidx = shift ? (pshift ? pi : cj) : lidx;
                }
                thr = __shfl_sync(0xffffffffu, lval, 31);
            }
        }
        knnIdx[((size_t)b*NSAMP + s)*KNNK + lane] = lidx;
    }
}

// ====================================================================
// Fused conv1x1 + BN + (residual) + ReLU. FFMA2, conflict-free LDS,
// W prefetched one kc ahead from pre-duplicated gmem buffer.
// Thread tx owns cols {tx*4..+3} and {64+tx*4..+3}.  (R8-proven form)
// ====================================================================
template<int GATHER, int POOL>
__global__ __launch_bounds__(256, 2) void conv_bn_t(
    const float* __restrict__ X,
    const float* __restrict__ feat, const int* __restrict__ knnIdx, const int* __restrict__ fpsIdx,
    const float2* __restrict__ Wt2,
    const float* __restrict__ gam, const float* __restrict__ bet,
    const float* __restrict__ mu,  const float* __restrict__ var,
    const float* __restrict__ R,   float* __restrict__ Y,
    int kls)
{
    extern __shared__ float sm[];
    float* Xs      = sm;                       // [c][col], stride 132
    float* s_scale = sm + 128*XS_STRIDE;
    float* s_shift = s_scale + 128;

    const int tid  = threadIdx.x;
    const int klen = 1 << kls;
    const int n0   = blockIdx.x << 7;

    if (GATHER) {
        const int gbase = n0 >> 5;                  // kls == 5 in gather mode
        const int b = gbase >> 11;
        const float* fb = feat + (size_t)b * NPTS * CIN;
        const int cc = tid & 63, jj = tid >> 6;
        for (int it = 0; it < 32; it++) {
            int col = it*4 + jj;
            int g = gbase + (col >> 5), k = col & 31;
            int p = __ldg(&knnIdx[g*KNNK + k]);
            Xs[cc*XS_STRIDE + col] = fb[p*CIN + cc];
        }
        {
            int g = gbase + jj;
            float v = fb[__ldg(&fpsIdx[g])*CIN + cc];
            float4* row = (float4*)(Xs + (cc + CIN)*XS_STRIDE + jj*32);
            float4 vv = make_float4(v, v, v, v);
#pragma unroll
            for (int k4 = 0; k4 < 8; k4++) row[k4] = vv;
        }
    } else {
        for (int idx = tid; idx < 16384; idx += 256) {
            int c = idx >> 7, col = idx & 127;
            int n = n0 + col;
            int g = n >> kls, k = n & (klen-1);
            Xs[c*XS_STRIDE + col] = X[((g << 7) + c) * klen + k];
        }
    }
    if (tid < 128) {
        float sc = gam[tid] / sqrtf(var[tid] + 1e-5f);
        s_scale[tid] = sc;
        s_shift[tid] = bet[tid] - mu[tid] * sc;
    }
    __syncthreads();

    const int tx = tid & 15, ty = tid >> 4;
    unsigned long long acc[8][4];               // [o][colpair]
#pragma unroll
    for (int i = 0; i < 8; i++)
#pragma unroll
        for (int j = 0; j < 4; j++) acc[i][j] = 0ull;

    const float* XsC = Xs + tx*4;
    const ulonglong2* __restrict__ Wc = (const ulonglong2*)(Wt2 + ty*8);

    ulonglong2 w01 = __ldg(Wc);
    ulonglong2 w23 = __ldg(Wc + 1);
    ulonglong2 w45 = __ldg(Wc + 2);
    ulonglong2 w67 = __ldg(Wc + 3);

#pragma unroll 2
    for (int kc = 0; kc < 128; kc++) {
        ulonglong2 xa = *(const ulonglong2*)(XsC + kc*XS_STRIDE);        // cols tx*4..+3
        ulonglong2 xb = *(const ulonglong2*)(XsC + kc*XS_STRIDE + 64);   // cols 64+tx*4..+3
        const ulonglong2* wn = Wc + (kc + 1)*64;       // prefetch next kc (pad row at end)
        ulonglong2 n01 = __ldg(wn);
        ulonglong2 n23 = __ldg(wn + 1);
        ulonglong2 n45 = __ldg(wn + 2);
        ulonglong2 n67 = __ldg(wn + 3);
        unsigned long long wv[8] = {w01.x, w01.y, w23.x, w23.y, w45.x, w45.y, w67.x, w67.y};
        unsigned long long xp[4] = {xa.x, xa.y, xb.x, xb.y};
#pragma unroll
        for (int i = 0; i < 8; i++)
#pragma unroll
            for (int j = 0; j < 4; j++)
                FFMA2(acc[i][j], wv[i], xp[j]);
        w01 = n01; w23 = n23; w45 = n45; w67 = n67;
    }

    const int ncolA = n0 + tx*4;
    const int ncolB = ncolA + 64;
    const int gA = ncolA >> kls, kA = ncolA & (klen-1);
    const int gB = ncolB >> kls, kB = ncolB & (klen-1);
#pragma unroll
    for (int i = 0; i < 8; i++) {
        const int o = ty*8 + i;
        const float sc = s_scale[o], sh = s_shift[o];
        const int addrA = ((gA << 7) + o) * klen + kA;
        const int addrB = ((gB << 7) + o) * klen + kB;
        float v[8];
#pragma unroll
        for (int j = 0; j < 4; j++) {
            unsigned lo, hi;
            UNPACK64(lo, hi, acc[i][j]);
            v[2*j]   = __uint_as_float(lo);
            v[2*j+1] = __uint_as_float(hi);
        }
#pragma unroll
        for (int j = 0; j < 8; j++) v[j] = fmaf(v[j], sc, sh);
        if (R) {
            float4 rA = *(const float4*)(R + addrA);
            float4 rB = *(const float4*)(R + addrB);
            v[0]+=rA.x; v[1]+=rA.y; v[2]+=rA.z; v[3]+=rA.w;
            v[4]+=rB.x; v[5]+=rB.y; v[6]+=rB.z; v[7]+=rB.w;
        }
#pragma unroll
        for (int j = 0; j < 8; j++) v[j] = fmaxf(v[j], 0.f);

        if (POOL) {
            // klen==32: group A = 32 cols covered by tx-octet {0-7} or {8-15}
            float mA = fmaxf(fmaxf(v[0],v[1]), fmaxf(v[2],v[3]));
            float mB = fmaxf(fmaxf(v[4],v[5]), fmaxf(v[6],v[7]));
            mA = fmaxf(mA, __shfl_xor_sync(0xffffffffu, mA, 1));
            mB = fmaxf(mB, __shfl_xor_sync(0xffffffffu, mB, 1));
            mA = fmaxf(mA, __shfl_xor_sync(0xffffffffu, mA, 2));
            mB = fmaxf(mB, __shfl_xor_sync(0xffffffffu, mB, 2));
            mA = fmaxf(mA, __shfl_xor_sync(0xffffffffu, mA, 4));
            mB = fmaxf(mB, __shfl_xor_sync(0xffffffffu, mB, 4));
            if ((tx & 7) == 0) {
                int bbA = gA >> 11, sA = gA & 2047;
                int bbB = gB >> 11, sB = gB & 2047;
                Y[((bbA << 7) + o) * 2048 + sA] = mA;
                Y[((bbB << 7) + o) * 2048 + sB] = mB;
            }
        } else {
            *(float4*)(Y + addrA) = make_float4(v[0],v[1],v[2],v[3]);
            *(float4*)(Y + addrB) = make_float4(v[4],v[5],v[6],v[7]);
        }
    }
}

// ====================================================================
extern "C" void kernel_launch(void* const* d_in, const int* in_sizes, int n_in,
                              void* d_out, int out_size)
{
    // setup_inputs() dict-insertion order
    const float* xyz    = (const float*)d_in[0];
    const float* feat   = (const float*)d_in[1];
    const float* te_w   = (const float*)d_in[2];
    const float* te_g   = (const float*)d_in[3];
    const float* te_b   = (const float*)d_in[4];
    const float* te_m   = (const float*)d_in[5];
    const float* te_v   = (const float*)d_in[6];
    const float* pre_w1 = (const float*)d_in[7];
    const float* pre_w2 = (const float*)d_in[8];
    const float* pre_g1 = (const float*)d_in[9];
    const float* pre_g2 = (const float*)d_in[10];
    const float* pre_b1 = (const float*)d_in[11];
    const float* pre_b2 = (const float*)d_in[12];
    const float* pre_m1 = (const float*)d_in[13];
    const float* pre_m2 = (const float*)d_in[14];
    const float* pre_v1 = (const float*)d_in[15];
    const float* pre_v2 = (const float*)d_in[16];
    const float* pos_w1 = (const float*)d_in[17];
    const float* pos_w2 = (const float*)d_in[18];
    const float* pos_g1 = (const float*)d_in[19];
    const float* pos_g2 = (const float*)d_in[20];
    const float* pos_b1 = (const float*)d_in[21];
    const float* pos_b2 = (const float*)d_in[22];
    const float* pos_m1 = (const float*)d_in[23];
    const float* pos_m2 = (const float*)d_in[24];
    const float* pos_v1 = (const float*)d_in[25];
    const float* pos_v2 = (const float*)d_in[26];

    float* out_xyz = (float*)d_out;                    // (8,2048,3)
    float* out_x   = (float*)d_out + BATCH*NSAMP*3;    // (8,128,2048)

    float *A, *Bb, *P, *D; int *fp, *kn; float2 *wt;
    cudaGetSymbolAddress((void**)&A,  g_bufA);
    cudaGetSymbolAddress((void**)&Bb, g_bufB);
    cudaGetSymbolAddress((void**)&P,  g_bufP);
    cudaGetSymbolAddress((void**)&D,  g_bufD);
    cudaGetSymbolAddress((void**)&fp, g_fps);
    cudaGetSymbolAddress((void**)&kn, g_knn);
    cudaGetSymbolAddress((void**)&wt, g_wt2);

    const int FPS_SMEM  = (3*NPTS + 128) * 4;             // ~99 KB
    const int KNN_SMEM  = 3 * NPTS * 4;                   // 96 KB
    const int CONV_SMEM = (128*XS_STRIDE + 256) * 4;      // ~68.6 KB
    cudaFuncSetAttribute(fps_kernel,      cudaFuncAttributeMaxDynamicSharedMemorySize, FPS_SMEM);
    cudaFuncSetAttribute(knn_kernel,      cudaFuncAttributeMaxDynamicSharedMemorySize, KNN_SMEM);
    cudaFuncSetAttribute(conv_bn_t<0,0>,  cudaFuncAttributeMaxDynamicSharedMemorySize, CONV_SMEM);
    cudaFuncSetAttribute(conv_bn_t<1,0>,  cudaFuncAttributeMaxDynamicSharedMemorySize, CONV_SMEM);
    cudaFuncSetAttribute(conv_bn_t<0,1>,  cudaFuncAttributeMaxDynamicSharedMemorySize, CONV_SMEM);

    // weight pre-transform (stage order: te, pw1[0], pw2[0], pw1[1], pw2[1], qw1[0], qw2[0], qw1[1], qw2[1])
    WPtrs wp;
    wp.w[0] = te_w;
    wp.w[1] = pre_w1;          wp.w[2] = pre_w2;
    wp.w[3] = pre_w1 + 16384;  wp.w[4] = pre_w2 + 16384;
    wp.w[5] = pos_w1;          wp.w[6] = pos_w2;
    wp.w[7] = pos_w1 + 16384;  wp.w[8] = pos_w2 + 16384;
    wtrans_kernel<<<(9*16384)/256, 256>>>(wp, wt);

    fps_kernel<<<BATCH, 1024, FPS_SMEM>>>(xyz, out_xyz, fp);
    knn_kernel<<<256, 256, KNN_SMEM>>>(xyz, out_xyz, kn);

    // te (gather fused) + 2 pre res-blocks; 524288 cols, kls=5
    conv_bn_t<1,0><<<4096, 256, CONV_SMEM>>>(nullptr, feat, kn, fp, wt + 0*16384, te_g, te_b, te_m, te_v, nullptr, Bb, 5);
    conv_bn_t<0,0><<<4096, 256, CONV_SMEM>>>(Bb, nullptr, nullptr, nullptr, wt + 1*16384, pre_g1,     pre_b1,     pre_m1,     pre_v1,     nullptr, A,  5);
    conv_bn_t<0,0><<<4096, 256, CONV_SMEM>>>(A,  nullptr, nullptr, nullptr, wt + 2*16384, pre_g2,     pre_b2,     pre_m2,     pre_v2,     Bb,      Bb, 5);
    conv_bn_t<0,0><<<4096, 256, CONV_SMEM>>>(Bb, nullptr, nullptr, nullptr, wt + 3*16384, pre_g1+128, pre_b1+128, pre_m1+128, pre_v1+128, nullptr, A,  5);
    // last pre conv: maxpool fused into epilogue, writes P directly
    conv_bn_t<0,1><<<4096, 256, CONV_SMEM>>>(A,  nullptr, nullptr, nullptr, wt + 4*16384, pre_g2+128, pre_b2+128, pre_m2+128, pre_v2+128, Bb,      P,  5);

    // pos: 2 res-blocks on (8,128,2048); 16384 cols, kls=11
    conv_bn_t<0,0><<<128, 256, CONV_SMEM>>>(P, nullptr, nullptr, nullptr, wt + 5*16384, pos_g1,     pos_b1,     pos_m1,     pos_v1,     nullptr, D,     11);
    conv_bn_t<0,0><<<128, 256, CONV_SMEM>>>(D, nullptr, nullptr, nullptr, wt + 6*16384, pos_g2,     pos_b2,     pos_m2,     pos_v2,     P,       P,     11);
    conv_bn_t<0,0><<<128, 256, CONV_SMEM>>>(P, nullptr, nullptr, nullptr, wt + 7*16384, pos_g1+128, pos_b1+128, pos_m1+128, pos_v1+128, nullptr, D,     11);
    conv_bn_t<0,0><<<128, 256, CONV_SMEM>>>(D, nullptr, nullptr, nullptr, wt + 8*16384, pos_g2+128, pos_b2+128, pos_m2+128, pos_v2+128, P,       out_x, 11);
}